// round 8
// baseline (speedup 1.0000x reference)
#include <cuda_runtime.h>
#include <cuda_fp16.h>
#include <cstdint>

#define N_NODES_MAX 100000
#define FEAT 128
#define CAP 96   // max in-degree bucket capacity (Poisson(16): P(deg>=96) ~ e^-40)

// Scratch (static device globals; no allocations allowed)
__device__ __align__(16) __half g_hr[(size_t)N_NODES_MAX * FEAT];  // fp16 hr
__device__ __align__(16) int    g_cnt[N_NODES_MAX];
__device__ __align__(16) int    g_bucket[(size_t)N_NODES_MAX * CAP];

#define LDS 136
#define GEMM_SMEM_BYTES (2 * 128 * LDS * 2)   // 69,632 B
#define EDGES_PER_THREAD 16
#define EDGES_PER_BLOCK (256 * EDGES_PER_THREAD)  // 4096

// ---------------------------------------------------------------------------
// GEMM block body: hr[g*128 : g*128+128] = relu(h @ W^T + b) via mma.sync
// m16n8k16. 8 warps (4x2), warp tile 32x64. fp16 smem (stride 136), K=128
// fully smem-resident: single sync, 8 k-steps. fp32 accum, fp16 store.
// ---------------------------------------------------------------------------
__device__ __forceinline__
void gemm_block(const float* __restrict__ h, const float* __restrict__ W,
                const float* __restrict__ bias, __half* __restrict__ hr,
                int M, int g)
{
    extern __shared__ __half smem_h[];
    __half* Ah = smem_h;               // [128][136]
    __half* Ws = smem_h + 128 * LDS;   // [128][136]

    const int tid  = threadIdx.x;
    const int bm0  = g * 128;
    const int lane = tid & 31;
    const int wid  = tid >> 5;         // 0..7
    const int m0w  = (wid >> 1) * 32;  // warp row origin within tile
    const int n0w  = (wid & 1) * 64;   // warp col origin

    // --- Fill smem: convert fp32 -> fp16 (h rows + full W) ---
#pragma unroll
    for (int it = 0; it < 16; it++) {
        int t   = tid + it * 256;      // 0..4095
        int row = t >> 5;              // 0..127
        int c4  = t & 31;              // float4 index within row
        int gr = bm0 + row;
        float4 v = make_float4(0.f, 0.f, 0.f, 0.f);
        if (gr < M) v = *(const float4*)(h + (size_t)gr * FEAT + c4 * 4);
        __half2 h0 = __float22half2_rn(make_float2(v.x, v.y));
        __half2 h1 = __float22half2_rn(make_float2(v.z, v.w));
        *(uint2*)&Ah[row * LDS + c4 * 4] = make_uint2(*(uint32_t*)&h0, *(uint32_t*)&h1);
        float4 w = *(const float4*)(W + (size_t)row * FEAT + c4 * 4);
        __half2 w0 = __float22half2_rn(make_float2(w.x, w.y));
        __half2 w1 = __float22half2_rn(make_float2(w.z, w.w));
        *(uint2*)&Ws[row * LDS + c4 * 4] = make_uint2(*(uint32_t*)&w0, *(uint32_t*)&w1);
    }
    __syncthreads();

    float acc[2][8][4];
#pragma unroll
    for (int mt = 0; mt < 2; mt++)
#pragma unroll
        for (int nt = 0; nt < 8; nt++)
#pragma unroll
            for (int q = 0; q < 4; q++) acc[mt][nt][q] = 0.f;

#pragma unroll
    for (int ks = 0; ks < 8; ks++) {
        const int k0 = ks * 16;
        uint32_t a[2][4];
#pragma unroll
        for (int mt = 0; mt < 2; mt++) {
            const __half* p = &Ah[(m0w + mt * 16 + (lane & 15)) * LDS + k0 + ((lane >> 4) << 3)];
            uint32_t addr = (uint32_t)__cvta_generic_to_shared(p);
            asm volatile("ldmatrix.sync.aligned.m8n8.x4.shared.b16 {%0,%1,%2,%3}, [%4];"
                         : "=r"(a[mt][0]), "=r"(a[mt][1]), "=r"(a[mt][2]), "=r"(a[mt][3])
                         : "r"(addr));
        }
        uint32_t bf[8][2];
#pragma unroll
        for (int bp = 0; bp < 4; bp++) {
            int nrow = n0w + bp * 16 + (lane & 7) + ((lane >> 4) << 3);
            int ncol = k0 + (((lane >> 3) & 1) << 3);
            const __half* p = &Ws[nrow * LDS + ncol];
            uint32_t addr = (uint32_t)__cvta_generic_to_shared(p);
            uint32_t r0, r1, r2, r3;
            asm volatile("ldmatrix.sync.aligned.m8n8.x4.shared.b16 {%0,%1,%2,%3}, [%4];"
                         : "=r"(r0), "=r"(r1), "=r"(r2), "=r"(r3) : "r"(addr));
            bf[bp * 2][0] = r0; bf[bp * 2][1] = r1;
            bf[bp * 2 + 1][0] = r2; bf[bp * 2 + 1][1] = r3;
        }
#pragma unroll
        for (int mt = 0; mt < 2; mt++)
#pragma unroll
            for (int nt = 0; nt < 8; nt++) {
                asm volatile(
                    "mma.sync.aligned.m16n8k16.row.col.f32.f16.f16.f32 "
                    "{%0,%1,%2,%3}, {%4,%5,%6,%7}, {%8,%9}, {%0,%1,%2,%3};"
                    : "+f"(acc[mt][nt][0]), "+f"(acc[mt][nt][1]),
                      "+f"(acc[mt][nt][2]), "+f"(acc[mt][nt][3])
                    : "r"(a[mt][0]), "r"(a[mt][1]), "r"(a[mt][2]), "r"(a[mt][3]),
                      "r"(bf[nt][0]), "r"(bf[nt][1]));
            }
    }

    // --- Epilogue: +bias, relu, fp16 store ---
    const int gid = lane >> 2;
    const int tg  = lane & 3;
#pragma unroll
    for (int mt = 0; mt < 2; mt++) {
#pragma unroll
        for (int nt = 0; nt < 8; nt++) {
            int c = n0w + nt * 8 + tg * 2;
            float2 bb = *(const float2*)&bias[c];
            int r0 = bm0 + m0w + mt * 16 + gid;
            if (r0 < M) {
                float x = fmaxf(acc[mt][nt][0] + bb.x, 0.f);
                float y = fmaxf(acc[mt][nt][1] + bb.y, 0.f);
                *(__half2*)&hr[(size_t)r0 * FEAT + c] = __float22half2_rn(make_float2(x, y));
            }
            int r1 = r0 + 8;
            if (r1 < M) {
                float x = fmaxf(acc[mt][nt][2] + bb.x, 0.f);
                float y = fmaxf(acc[mt][nt][3] + bb.y, 0.f);
                *(__half2*)&hr[(size_t)r1 * FEAT + c] = __float22half2_rn(make_float2(x, y));
            }
        }
    }
}

// ---------------------------------------------------------------------------
// Bucket block body: 16 edges per thread; slot = cnt[dst]++, store src.
// ---------------------------------------------------------------------------
__device__ __forceinline__
void bucket_block(const int* __restrict__ src, const int* __restrict__ dst,
                  int n_edges, int M, int bucket_bid)
{
    int t  = bucket_bid * 256 + threadIdx.x;
    int e0 = t * EDGES_PER_THREAD;
    if (e0 >= n_edges) return;

    if (e0 + EDGES_PER_THREAD <= n_edges) {
#pragma unroll
        for (int c = 0; c < EDGES_PER_THREAD / 4; c++) {
            int4 s4 = *(const int4*)(src + e0 + c * 4);
            int4 d4 = *(const int4*)(dst + e0 + c * 4);
            int ss[4] = {s4.x, s4.y, s4.z, s4.w};
            int dd[4] = {d4.x, d4.y, d4.z, d4.w};
            int slot[4];
#pragma unroll
            for (int i = 0; i < 4; i++) {
                if ((unsigned)ss[i] >= (unsigned)M) ss[i] = 0;
                if ((unsigned)dd[i] >= (unsigned)M) dd[i] = 0;
                slot[i] = atomicAdd(&g_cnt[dd[i]], 1);
            }
#pragma unroll
            for (int i = 0; i < 4; i++)
                if (slot[i] < CAP) g_bucket[(size_t)dd[i] * CAP + slot[i]] = ss[i];
        }
    } else {
        for (int e = e0; e < n_edges; e++) {
            int s = src[e], d = dst[e];
            if ((unsigned)s >= (unsigned)M) s = 0;
            if ((unsigned)d >= (unsigned)M) d = 0;
            int slot = atomicAdd(&g_cnt[d], 1);
            if (slot < CAP) g_bucket[(size_t)d * CAP + slot] = s;
        }
    }
}

// ---------------------------------------------------------------------------
// Fused kernel: per group of 3 blocks -> 1 bucket block + 2 GEMM tiles.
// Bucket blocks are L2-latency-bound (5% issue); GEMM is tensor-pipe-bound.
// Interleaving keeps both resident so bucket time hides under the GEMM.
// ---------------------------------------------------------------------------
__global__ __launch_bounds__(256, 3)
void fused_gemm_bucket_kernel(const float* __restrict__ h, const float* __restrict__ W,
                              const float* __restrict__ bias, __half* __restrict__ hr,
                              const int* __restrict__ src, const int* __restrict__ dst,
                              int M, int n_edges, int n_gemm, int n_bucket)
{
    int bid = blockIdx.x;
    int q = bid / 3, r = bid % 3;
    int gid;
    if (q < n_bucket) {
        if (r == 0) { bucket_block(src, dst, n_edges, M, q); return; }
        gid = 2 * q + r - 1;
    } else {
        gid = bid - n_bucket;
    }
    if (gid < n_gemm) gemm_block(h, W, bias, hr, M, gid);
}

// ---------------------------------------------------------------------------
// Gather-mean + finalize fused. One warp per node; lane owns 4 features
// (8B fp16 in, 16B fp32 out). 8-deep load pipeline, int4 index loads.
// ---------------------------------------------------------------------------
__global__ __launch_bounds__(256)
void gather_mean_kernel(const __half* __restrict__ hr, float* __restrict__ out, int M)
{
    int node = (blockIdx.x * blockDim.x + threadIdx.x) >> 5;
    int lane = threadIdx.x & 31;
    if (node >= M) return;

    int deg  = g_cnt[node];
    int degc = deg < CAP ? deg : CAP;
    const int* bkt = &g_bucket[(size_t)node * CAP];

    float4 acc = make_float4(0.f, 0.f, 0.f, 0.f);
    int k = 0;

    for (; k + 8 <= degc; k += 8) {
        int4 i0 = *(const int4*)(bkt + k);
        int4 i1 = *(const int4*)(bkt + k + 4);
        uint2 r0 = *((const uint2*)(hr + (size_t)i0.x * FEAT) + lane);
        uint2 r1 = *((const uint2*)(hr + (size_t)i0.y * FEAT) + lane);
        uint2 r2 = *((const uint2*)(hr + (size_t)i0.z * FEAT) + lane);
        uint2 r3 = *((const uint2*)(hr + (size_t)i0.w * FEAT) + lane);
        uint2 r4 = *((const uint2*)(hr + (size_t)i1.x * FEAT) + lane);
        uint2 r5 = *((const uint2*)(hr + (size_t)i1.y * FEAT) + lane);
        uint2 r6 = *((const uint2*)(hr + (size_t)i1.z * FEAT) + lane);
        uint2 r7 = *((const uint2*)(hr + (size_t)i1.w * FEAT) + lane);
#define ACC8(r) { \
        float2 _a = __half22float2(*(const __half2*)&(r).x); \
        float2 _b = __half22float2(*(const __half2*)&(r).y); \
        acc.x += _a.x; acc.y += _a.y; acc.z += _b.x; acc.w += _b.y; }
        ACC8(r0) ACC8(r1) ACC8(r2) ACC8(r3) ACC8(r4) ACC8(r5) ACC8(r6) ACC8(r7)
    }
    for (; k + 4 <= degc; k += 4) {
        int4 i0 = *(const int4*)(bkt + k);
        uint2 r0 = *((const uint2*)(hr + (size_t)i0.x * FEAT) + lane);
        uint2 r1 = *((const uint2*)(hr + (size_t)i0.y * FEAT) + lane);
        uint2 r2 = *((const uint2*)(hr + (size_t)i0.z * FEAT) + lane);
        uint2 r3 = *((const uint2*)(hr + (size_t)i0.w * FEAT) + lane);
        ACC8(r0) ACC8(r1) ACC8(r2) ACC8(r3)
    }
    for (; k < degc; k++) {
        int s = bkt[k];
        uint2 r = *((const uint2*)(hr + (size_t)s * FEAT) + lane);
        ACC8(r)
    }
#undef ACC8

    float4 o;
    if (deg > 0) {
        float inv = 1.0f / (float)deg;
        o.x = acc.x * inv; o.y = acc.y * inv; o.z = acc.z * inv; o.w = acc.w * inv;
    } else {
        uint2 r = *((const uint2*)(hr + (size_t)node * FEAT) + lane);
        float2 a = __half22float2(*(const __half2*)&r.x);
        float2 bq = __half22float2(*(const __half2*)&r.y);
        o.x = a.x; o.y = a.y; o.z = bq.x; o.w = bq.y;
    }
    *((float4*)(out + (size_t)node * FEAT) + lane) = o;
}

// ---------------------------------------------------------------------------
// Launch: inputs in metadata order: h, h_in, src, dst, W, b
// ---------------------------------------------------------------------------
extern "C" void kernel_launch(void* const* d_in, const int* in_sizes, int n_in,
                              void* d_out, int out_size)
{
    const float* h   = (const float*)d_in[0];
    // d_in[1] = h_in (unused by reference)
    const int*   src = (const int*)d_in[2];
    const int*   dst = (const int*)d_in[3];
    const float* W   = (const float*)d_in[4];
    const float* b   = (const float*)d_in[5];
    float*       out = (float*)d_out;

    const int M       = in_sizes[0] / FEAT;
    const int n_edges = in_sizes[2];

    __half* hr;  cudaGetSymbolAddress((void**)&hr, g_hr);
    int*    cnt; cudaGetSymbolAddress((void**)&cnt, g_cnt);

    cudaFuncSetAttribute(fused_gemm_bucket_kernel,
                         cudaFuncAttributeMaxDynamicSharedMemorySize, GEMM_SMEM_BYTES);

    // Zero the per-node counters
    cudaMemsetAsync(cnt, 0, (size_t)M * sizeof(int));

    // Fused bucket + GEMM (1 bucket block per 2 GEMM tiles)
    int n_gemm   = (M + 127) / 128;                                // 782
    int n_bucket = (n_edges + EDGES_PER_BLOCK - 1) / EDGES_PER_BLOCK; // 391
    int grid     = n_gemm + n_bucket;
    fused_gemm_bucket_kernel<<<grid, 256, GEMM_SMEM_BYTES>>>(
        h, W, b, hr, src, dst, M, n_edges, n_gemm, n_bucket);

    // out[node] = deg>0 ? mean(hr[srcs]) : hr[node]
    int n_blocks = (M * 32 + 255) / 256;
    gather_mean_kernel<<<n_blocks, 256>>>(hr, out, M);
}

// round 9
// speedup vs baseline: 1.4926x; 1.4926x over previous
#include <cuda_runtime.h>
#include <cuda_fp16.h>
#include <cstdint>

#define N_NODES_MAX 100000
#define FEAT 128
#define CAP 96   // max in-degree bucket capacity (Poisson(16): P(deg>=96) ~ e^-40)

// Scratch (static device globals; no allocations allowed)
__device__ __align__(16) __half g_hr[(size_t)N_NODES_MAX * FEAT];  // fp16 hr
__device__ __align__(16) __half g_Wh[FEAT * FEAT];                 // fp16 W
__device__ __align__(16) int    g_cnt[N_NODES_MAX];                // static-0; reset by gather
__device__ __align__(16) int    g_bucket[(size_t)N_NODES_MAX * CAP];

#define LDS 136
#define GEMM_SMEM_BYTES (2 * 128 * LDS * 2)   // 69,632 B
#define EDGES_PER_THREAD 4
#define EDGES_PER_BLOCK (256 * EDGES_PER_THREAD)
#define WCONV_BLOCKS 16

// ---------------------------------------------------------------------------
// Kernel A: bucket fill (blocks [0, n_bucket)) + W fp32->fp16 preconvert
// (16 extra blocks). Bucket is L2-latency-bound; wconv rides along free.
// ---------------------------------------------------------------------------
__global__ __launch_bounds__(256)
void bucket_wconv_kernel(const int* __restrict__ src, const int* __restrict__ dst,
                         const float* __restrict__ W,
                         int n_edges, int M, int n_bucket)
{
    int bid = blockIdx.x;
    if (bid >= n_bucket) {
        // --- W convert: 16 blocks x 256 threads x 4 floats = 16384 elems ---
        int t   = (bid - n_bucket) * 256 + threadIdx.x;   // 0..4095
        int idx = t * 4;
        float4 w = *(const float4*)(W + idx);
        __half2 w0 = __float22half2_rn(make_float2(w.x, w.y));
        __half2 w1 = __float22half2_rn(make_float2(w.z, w.w));
        *(uint2*)&g_Wh[idx] = make_uint2(*(uint32_t*)&w0, *(uint32_t*)&w1);
        return;
    }

    int t  = bid * 256 + threadIdx.x;
    int e0 = t * EDGES_PER_THREAD;
    if (e0 >= n_edges) return;

    if (e0 + EDGES_PER_THREAD <= n_edges) {
        int4 s4 = *(const int4*)(src + e0);
        int4 d4 = *(const int4*)(dst + e0);
        int ss[4] = {s4.x, s4.y, s4.z, s4.w};
        int dd[4] = {d4.x, d4.y, d4.z, d4.w};
        int slot[4];
#pragma unroll
        for (int i = 0; i < 4; i++) {
            if ((unsigned)ss[i] >= (unsigned)M) ss[i] = 0;
            if ((unsigned)dd[i] >= (unsigned)M) dd[i] = 0;
            slot[i] = atomicAdd(&g_cnt[dd[i]], 1);
        }
#pragma unroll
        for (int i = 0; i < 4; i++)
            if (slot[i] < CAP) g_bucket[(size_t)dd[i] * CAP + slot[i]] = ss[i];
    } else {
        for (int e = e0; e < n_edges; e++) {
            int s = src[e], d = dst[e];
            if ((unsigned)s >= (unsigned)M) s = 0;
            if ((unsigned)d >= (unsigned)M) d = 0;
            int slot = atomicAdd(&g_cnt[d], 1);
            if (slot < CAP) g_bucket[(size_t)d * CAP + slot] = s;
        }
    }
}

// ---------------------------------------------------------------------------
// Kernel B: hr = relu(h @ W^T + b) via mma.sync m16n8k16.
// Block = 128x128, 8 warps (4x2), warp tile 32x64. W loaded as fp16 from
// g_Wh (preconverted). Epilogue staged through smem for coalesced stores.
// ---------------------------------------------------------------------------
__global__ __launch_bounds__(256, 2)
void gemm_mma_kernel(const float* __restrict__ h, const __half* __restrict__ Wh,
                     const float* __restrict__ bias, __half* __restrict__ hr, int M)
{
    extern __shared__ __half smem_h[];
    __half* Ah = smem_h;               // [128][136]
    __half* Ws = smem_h + 128 * LDS;   // [128][136]

    const int tid  = threadIdx.x;
    const int bm0  = blockIdx.x * 128;
    const int lane = tid & 31;
    const int wid  = tid >> 5;         // 0..7
    const int m0w  = (wid >> 1) * 32;  // warp row origin
    const int n0w  = (wid & 1) * 64;   // warp col origin

    // --- Fill smem: h fp32->fp16 (16 iters), W fp16 direct copy (8 iters) ---
#pragma unroll
    for (int it = 0; it < 16; it++) {
        int t   = tid + it * 256;      // 0..4095
        int row = t >> 5;              // 0..127
        int c4  = t & 31;
        int gr  = bm0 + row;
        float4 v = make_float4(0.f, 0.f, 0.f, 0.f);
        if (gr < M) v = *(const float4*)(h + (size_t)gr * FEAT + c4 * 4);
        __half2 h0 = __float22half2_rn(make_float2(v.x, v.y));
        __half2 h1 = __float22half2_rn(make_float2(v.z, v.w));
        *(uint2*)&Ah[row * LDS + c4 * 4] = make_uint2(*(uint32_t*)&h0, *(uint32_t*)&h1);
    }
#pragma unroll
    for (int it = 0; it < 8; it++) {
        int t   = tid + it * 256;      // 0..2047
        int row = t >> 4;              // 0..127
        int c8  = t & 15;              // uint4 (8 halves) index
        uint4 v = *(const uint4*)(Wh + row * FEAT + c8 * 8);
        *(uint4*)&Ws[row * LDS + c8 * 8] = v;
    }
    __syncthreads();

    float acc[2][8][4];
#pragma unroll
    for (int mt = 0; mt < 2; mt++)
#pragma unroll
        for (int nt = 0; nt < 8; nt++)
#pragma unroll
            for (int q = 0; q < 4; q++) acc[mt][nt][q] = 0.f;

#pragma unroll
    for (int ks = 0; ks < 8; ks++) {
        const int k0 = ks * 16;
        uint32_t a[2][4];
#pragma unroll
        for (int mt = 0; mt < 2; mt++) {
            const __half* p = &Ah[(m0w + mt * 16 + (lane & 15)) * LDS + k0 + ((lane >> 4) << 3)];
            uint32_t addr = (uint32_t)__cvta_generic_to_shared(p);
            asm volatile("ldmatrix.sync.aligned.m8n8.x4.shared.b16 {%0,%1,%2,%3}, [%4];"
                         : "=r"(a[mt][0]), "=r"(a[mt][1]), "=r"(a[mt][2]), "=r"(a[mt][3])
                         : "r"(addr));
        }
        uint32_t bf[8][2];
#pragma unroll
        for (int bp = 0; bp < 4; bp++) {
            int nrow = n0w + bp * 16 + (lane & 7) + ((lane >> 4) << 3);
            int ncol = k0 + (((lane >> 3) & 1) << 3);
            const __half* p = &Ws[nrow * LDS + ncol];
            uint32_t addr = (uint32_t)__cvta_generic_to_shared(p);
            uint32_t r0, r1, r2, r3;
            asm volatile("ldmatrix.sync.aligned.m8n8.x4.shared.b16 {%0,%1,%2,%3}, [%4];"
                         : "=r"(r0), "=r"(r1), "=r"(r2), "=r"(r3) : "r"(addr));
            bf[bp * 2][0] = r0; bf[bp * 2][1] = r1;
            bf[bp * 2 + 1][0] = r2; bf[bp * 2 + 1][1] = r3;
        }
#pragma unroll
        for (int mt = 0; mt < 2; mt++)
#pragma unroll
            for (int nt = 0; nt < 8; nt++) {
                asm volatile(
                    "mma.sync.aligned.m16n8k16.row.col.f32.f16.f16.f32 "
                    "{%0,%1,%2,%3}, {%4,%5,%6,%7}, {%8,%9}, {%0,%1,%2,%3};"
                    : "+f"(acc[mt][nt][0]), "+f"(acc[mt][nt][1]),
                      "+f"(acc[mt][nt][2]), "+f"(acc[mt][nt][3])
                    : "r"(a[mt][0]), "r"(a[mt][1]), "r"(a[mt][2]), "r"(a[mt][3]),
                      "r"(bf[nt][0]), "r"(bf[nt][1]));
            }
    }

    // --- Epilogue: +bias, relu -> stage fp16 in smem -> coalesced stores ---
    __syncthreads();   // done reading Ah/Ws; reuse Ah as the staging buffer
    const int gid = lane >> 2;
    const int tg  = lane & 3;
#pragma unroll
    for (int mt = 0; mt < 2; mt++) {
#pragma unroll
        for (int nt = 0; nt < 8; nt++) {
            int c = n0w + nt * 8 + tg * 2;
            float2 bb = *(const float2*)&bias[c];
            int lr0 = m0w + mt * 16 + gid;
            float x0 = fmaxf(acc[mt][nt][0] + bb.x, 0.f);
            float y0 = fmaxf(acc[mt][nt][1] + bb.y, 0.f);
            *(__half2*)&Ah[lr0 * LDS + c] = __float22half2_rn(make_float2(x0, y0));
            float x1 = fmaxf(acc[mt][nt][2] + bb.x, 0.f);
            float y1 = fmaxf(acc[mt][nt][3] + bb.y, 0.f);
            *(__half2*)&Ah[(lr0 + 8) * LDS + c] = __float22half2_rn(make_float2(x1, y1));
        }
    }
    __syncthreads();
    // 128 rows x 128 halves = 2048 uint4; 8 per thread, fully coalesced STG
#pragma unroll
    for (int it = 0; it < 8; it++) {
        int t   = tid + it * 256;      // 0..2047
        int row = t >> 4;
        int c8  = t & 15;
        int gr  = bm0 + row;
        if (gr < M) {
            uint4 v = *(const uint4*)&Ah[row * LDS + c8 * 8];
            *(uint4*)(hr + (size_t)gr * FEAT + c8 * 8) = v;
        }
    }
}

// ---------------------------------------------------------------------------
// Kernel C: gather-mean + finalize. One warp per node; lane owns 4 features
// (8B fp16 in, 16B fp32 out). 8-deep load pipeline, int4 index loads.
// Resets g_cnt[node] = 0 at the end (prepares next graph replay; removes the
// separate memset launch). State invariant: cnt==0 on entry and exit.
// ---------------------------------------------------------------------------
__global__ __launch_bounds__(256)
void gather_mean_kernel(const __half* __restrict__ hr, float* __restrict__ out, int M)
{
    int node = (blockIdx.x * blockDim.x + threadIdx.x) >> 5;
    int lane = threadIdx.x & 31;
    if (node >= M) return;

    int deg  = g_cnt[node];
    int degc = deg < CAP ? deg : CAP;
    const int* bkt = &g_bucket[(size_t)node * CAP];

    float4 acc = make_float4(0.f, 0.f, 0.f, 0.f);
    int k = 0;

    for (; k + 8 <= degc; k += 8) {
        int4 i0 = *(const int4*)(bkt + k);
        int4 i1 = *(const int4*)(bkt + k + 4);
        uint2 r0 = *((const uint2*)(hr + (size_t)i0.x * FEAT) + lane);
        uint2 r1 = *((const uint2*)(hr + (size_t)i0.y * FEAT) + lane);
        uint2 r2 = *((const uint2*)(hr + (size_t)i0.z * FEAT) + lane);
        uint2 r3 = *((const uint2*)(hr + (size_t)i0.w * FEAT) + lane);
        uint2 r4 = *((const uint2*)(hr + (size_t)i1.x * FEAT) + lane);
        uint2 r5 = *((const uint2*)(hr + (size_t)i1.y * FEAT) + lane);
        uint2 r6 = *((const uint2*)(hr + (size_t)i1.z * FEAT) + lane);
        uint2 r7 = *((const uint2*)(hr + (size_t)i1.w * FEAT) + lane);
#define ACC8(r) { \
        float2 _a = __half22float2(*(const __half2*)&(r).x); \
        float2 _b = __half22float2(*(const __half2*)&(r).y); \
        acc.x += _a.x; acc.y += _a.y; acc.z += _b.x; acc.w += _b.y; }
        ACC8(r0) ACC8(r1) ACC8(r2) ACC8(r3) ACC8(r4) ACC8(r5) ACC8(r6) ACC8(r7)
    }
    for (; k + 4 <= degc; k += 4) {
        int4 i0 = *(const int4*)(bkt + k);
        uint2 r0 = *((const uint2*)(hr + (size_t)i0.x * FEAT) + lane);
        uint2 r1 = *((const uint2*)(hr + (size_t)i0.y * FEAT) + lane);
        uint2 r2 = *((const uint2*)(hr + (size_t)i0.z * FEAT) + lane);
        uint2 r3 = *((const uint2*)(hr + (size_t)i0.w * FEAT) + lane);
        ACC8(r0) ACC8(r1) ACC8(r2) ACC8(r3)
    }
    for (; k < degc; k++) {
        int s = bkt[k];
        uint2 r = *((const uint2*)(hr + (size_t)s * FEAT) + lane);
        ACC8(r)
    }
#undef ACC8

    float4 o;
    if (deg > 0) {
        float inv = 1.0f / (float)deg;
        o.x = acc.x * inv; o.y = acc.y * inv; o.z = acc.z * inv; o.w = acc.w * inv;
    } else {
        uint2 r = *((const uint2*)(hr + (size_t)node * FEAT) + lane);
        float2 a = __half22float2(*(const __half2*)&r.x);
        float2 bq = __half22float2(*(const __half2*)&r.y);
        o.x = a.x; o.y = a.y; o.z = bq.x; o.w = bq.y;
    }
    *((float4*)(out + (size_t)node * FEAT) + lane) = o;

    if (lane == 0) g_cnt[node] = 0;   // reset for next replay
}

// ---------------------------------------------------------------------------
// Launch: inputs in metadata order: h, h_in, src, dst, W, b  (3 launches)
// ---------------------------------------------------------------------------
extern "C" void kernel_launch(void* const* d_in, const int* in_sizes, int n_in,
                              void* d_out, int out_size)
{
    const float* h   = (const float*)d_in[0];
    // d_in[1] = h_in (unused by reference)
    const int*   src = (const int*)d_in[2];
    const int*   dst = (const int*)d_in[3];
    const float* W   = (const float*)d_in[4];
    const float* b   = (const float*)d_in[5];
    float*       out = (float*)d_out;

    const int M       = in_sizes[0] / FEAT;
    const int n_edges = in_sizes[2];

    __half* hr; cudaGetSymbolAddress((void**)&hr, g_hr);
    __half* Wh; cudaGetSymbolAddress((void**)&Wh, g_Wh);

    cudaFuncSetAttribute(gemm_mma_kernel,
                         cudaFuncAttributeMaxDynamicSharedMemorySize, GEMM_SMEM_BYTES);

    // A: bucket the edges + preconvert W to fp16
    int n_bucket = (n_edges + EDGES_PER_BLOCK - 1) / EDGES_PER_BLOCK;
    bucket_wconv_kernel<<<n_bucket + WCONV_BLOCKS, 256>>>(src, dst, W, n_edges, M, n_bucket);

    // B: hr = relu(h @ W^T + b), fp16
    gemm_mma_kernel<<<(M + 127) / 128, 256, GEMM_SMEM_BYTES>>>(h, Wh, b, hr, M);

    // C: out = deg>0 ? mean(hr[srcs]) : hr[node]; resets cnt
    int n_blocks = (M * 32 + 255) / 256;
    gather_mean_kernel<<<n_blocks, 256>>>(hr, out, M);
}